// round 1
// baseline (speedup 1.0000x reference)
#include <cuda_runtime.h>
#include <cstdint>

#define IN_SIZE  256
#define N_NODES  1024
#define DEG      32
#define BATCH    16384
#define OUT_SIZE 16

#define BT      32                      // batch columns per CTA
#define STRIDE  33                      // floats per activation row (+1 pad: bank = (idx+col)%32)
#define ROWB    (STRIDE * 4)            // 132 bytes per row
#define NROWS   (IN_SIZE + N_NODES)     // 1280
#define SMEM_BYTES (NROWS * ROWB)       // 168,960 B

// (byte_offset = idx*132, weight) pairs, packed by prepass. +256 pad for prefetch overrun.
__device__ uint2 g_pairs[N_NODES * DEG + 256];

__global__ void pack_pairs(const int* __restrict__ idx, const float* __restrict__ w) {
    int t = blockIdx.x * blockDim.x + threadIdx.x;
    if (t < N_NODES * DEG) {
        g_pairs[t] = make_uint2((unsigned)idx[t] * (unsigned)ROWB, __float_as_uint(w[t]));
    } else if (t < N_NODES * DEG + 256) {
        g_pairs[t] = make_uint2(0u, 0u);
    }
}

// Exact identity tanh(x) = 1 - 2/(exp(2x)+1); MUFU EX2 + MUFU RCP, ~1e-6 abs error.
// Saturates correctly: exp->inf => 1, exp->0 => -1.
__device__ __forceinline__ float ftanh(float x) {
    float e = __expf(2.0f * x);
    return 1.0f - __fdividef(2.0f, e + 1.0f);
}

extern __shared__ float As[];   // [NROWS][STRIDE] activations, column-partitioned by lane

__global__ void __launch_bounds__(256, 1)
ne_kernel(const float* __restrict__ x, float* __restrict__ out) {
    const int tid = threadIdx.x;
    const int b0  = blockIdx.x * BT;

    // ---- Stage network inputs transposed into SMEM: As[i][bl] = x[b0+bl][i] ----
    {
        int bl = tid >> 3;          // 0..31 : batch column
        int ts = tid & 7;           // 0..7  : chunk within row
        const float4* xr = (const float4*)(x + (size_t)(b0 + bl) * IN_SIZE);
        #pragma unroll
        for (int k = ts; k < IN_SIZE / 4; k += 8) {
            float4 v = xr[k];
            int i = k * 4;
            As[(i + 0) * STRIDE + bl] = v.x;
            As[(i + 1) * STRIDE + bl] = v.y;
            As[(i + 2) * STRIDE + bl] = v.z;
            As[(i + 3) * STRIDE + bl] = v.w;
        }
    }
    __syncthreads();

    // ---- Lane layout: 8 deg-groups x 4 batch cols per warp; 8 warps = 32 cols ----
    const int lane = tid & 31;
    const int warp = tid >> 5;
    const int dg   = lane >> 2;          // 0..7  deg group (handles deg dg*4 .. dg*4+3)
    const int bb   = lane & 3;           // 0..3
    const int col  = warp * 4 + bb;      // 0..31 batch column (exclusive per warp)
    const bool writer = (dg == 0);

    const char* Ac = (const char*)As + col * 4;                    // gather base
    char*       Aw = (char*)As + col * 4 + IN_SIZE * ROWB;         // write ptr (row 256)

    // pair stream: node n, group dg -> uint4 pair-of-pairs at [n*16 + dg*2], [n*16 + dg*2 + 1]
    const uint4* pp = (const uint4*)g_pairs + dg * 2;

    // 4-node software pipeline on the (idx,w) pair stream (hides L2 latency ~250cy)
    uint4 c0[4], c1[4];
    #pragma unroll
    for (int u = 0; u < 4; u++) { c0[u] = pp[u * 16]; c1[u] = pp[u * 16 + 1]; }
    pp += 64;

    for (int base = 0; base < N_NODES; base += 4) {
        uint4 n0[4], n1[4];
        #pragma unroll
        for (int u = 0; u < 4; u++) { n0[u] = pp[u * 16]; n1[u] = pp[u * 16 + 1]; }
        pp += 64;

        #pragma unroll
        for (int u = 0; u < 4; u++) {
            uint4 pa = c0[u], pb = c1[u];
            float v0 = *(const float*)(Ac + pa.x);
            float v1 = *(const float*)(Ac + pa.z);
            float v2 = *(const float*)(Ac + pb.x);
            float v3 = *(const float*)(Ac + pb.z);
            float a0 = __uint_as_float(pa.y) * v0 + __uint_as_float(pa.w) * v1;
            float a1 = __uint_as_float(pb.y) * v2 + __uint_as_float(pb.w) * v3;
            float s = a0 + a1;
            // butterfly-reduce across the 8 deg groups (b preserved)
            s += __shfl_xor_sync(0xffffffffu, s, 4);
            s += __shfl_xor_sync(0xffffffffu, s, 8);
            s += __shfl_xor_sync(0xffffffffu, s, 16);
            float t = ftanh(s);
            if (writer) *(float*)Aw = t;   // same-warp, in-order SMEM; cols are warp-private
            Aw += ROWB;
        }
        #pragma unroll
        for (int u = 0; u < 4; u++) { c0[u] = n0[u]; c1[u] = n1[u]; }
    }

    // ---- Emit last OUT_SIZE node outputs: out[o][b0+col], lanes (dg,bb) -> (o, col) ----
    #pragma unroll
    for (int it = 0; it < 2; it++) {
        int o = it * 8 + dg;
        float v = *(const float*)((const char*)As +
                     (size_t)(IN_SIZE + N_NODES - OUT_SIZE + o) * ROWB + col * 4);
        out[(size_t)o * BATCH + b0 + col] = v;
    }
}

extern "C" void kernel_launch(void* const* d_in, const int* in_sizes, int n_in,
                              void* d_out, int out_size) {
    const float* x   = (const float*)d_in[0];   // [16384, 256] f32
    const float* w   = (const float*)d_in[1];   // [1024, 32]   f32
    const int*   idx = (const int*)  d_in[2];   // [1024, 32]   i32
    float*       out = (float*)d_out;           // [16, 16384]  f32

    cudaFuncSetAttribute(ne_kernel, cudaFuncAttributeMaxDynamicSharedMemorySize, SMEM_BYTES);

    int pack_elems = N_NODES * DEG + 256;
    pack_pairs<<<(pack_elems + 255) / 256, 256>>>(idx, w);
    ne_kernel<<<BATCH / BT, 256, SMEM_BYTES>>>(x, out);
}

// round 2
// speedup vs baseline: 1.1282x; 1.1282x over previous
#include <cuda_runtime.h>
#include <cstdint>

#define IN_SIZE  256
#define N_NODES  1024
#define DEG      32
#define BATCH    16384
#define OUT_SIZE 16

#define BT      32                      // batch columns per CTA
#define STRIDE  33                      // floats per activation row (+1 pad: bank = (idx+col)%32)
#define ROWB    (STRIDE * 4)            // 132 bytes per row
#define NROWS   (IN_SIZE + N_NODES)     // 1280
#define NGROUPS (N_NODES / 4)           // 256
#define SMEM_ACT (NROWS * ROWB)         // 168,960 B
#define SMEM_BYTES (SMEM_ACT + NGROUPS * 4)

// (byte_offset = idx*132, weight) pairs; +256 uint2 pad for prefetch overrun.
__device__ uint2    g_pairs[N_NODES * DEG + 256];
__device__ unsigned g_flags[NGROUPS];   // 1 = group has an internal dependency

__global__ void pack_pairs(const int* __restrict__ idx, const float* __restrict__ w) {
    int t = blockIdx.x * blockDim.x + threadIdx.x;
    if (t < N_NODES * DEG) {
        g_pairs[t] = make_uint2((unsigned)idx[t] * (unsigned)ROWB, __float_as_uint(w[t]));
    } else if (t < N_NODES * DEG + 256) {
        g_pairs[t] = make_uint2(0u, 0u);
    }
    if (t < NGROUPS) g_flags[t] = 0u;
}

// Group g = nodes 4g..4g+3. Internal dep iff some node 4g+1..4g+3 reads row >= 256+4g.
__global__ void mark_flags(const int* __restrict__ idx) {
    int g = blockIdx.x;            // NGROUPS blocks
    int j = threadIdx.x;           // 96 threads: nodes 4g+1..4g+3 x 32 deg
    int n = 4 * g + 1 + (j >> 5);
    int d = j & 31;
    if (idx[n * DEG + d] >= IN_SIZE + 4 * g) g_flags[g] = 1u;  // benign same-value race
}

// Exact tanh(x) = 1 - 2/(exp(2x)+1); 2x MUFU, ~1e-6 abs error, saturates correctly.
__device__ __forceinline__ float ftanh(float x) {
    float e = __expf(2.0f * x);
    return 1.0f - __fdividef(2.0f, e + 1.0f);
}

__device__ __forceinline__ float wredux(float s) {
    s += __shfl_xor_sync(0xffffffffu, s, 4);
    s += __shfl_xor_sync(0xffffffffu, s, 8);
    s += __shfl_xor_sync(0xffffffffu, s, 16);
    return s;   // bit-identical across the 8 dg lanes (commutative same-order adds)
}

extern __shared__ float As[];   // [NROWS][STRIDE] activations + flag cache

__global__ void __launch_bounds__(256, 1)
ne_kernel(const float* __restrict__ x, float* __restrict__ out) {
    const int tid = threadIdx.x;
    const int b0  = blockIdx.x * BT;
    unsigned* s_flags = (unsigned*)(As + NROWS * STRIDE);

    // ---- Stage network inputs transposed: As[i][bl] = x[b0+bl][i] ----
    {
        int bl = tid >> 3;
        int ts = tid & 7;
        const float4* xr = (const float4*)(x + (size_t)(b0 + bl) * IN_SIZE);
        #pragma unroll
        for (int k = ts; k < IN_SIZE / 4; k += 8) {
            float4 v = xr[k];
            int i = k * 4;
            As[(i + 0) * STRIDE + bl] = v.x;
            As[(i + 1) * STRIDE + bl] = v.y;
            As[(i + 2) * STRIDE + bl] = v.z;
            As[(i + 3) * STRIDE + bl] = v.w;
        }
        if (tid < NGROUPS) s_flags[tid] = g_flags[tid];
    }
    __syncthreads();

    // ---- Lane layout: 8 deg-groups x 4 batch cols per warp; 8 warps = 32 cols ----
    const int lane = tid & 31;
    const int warp = tid >> 5;
    const int dg   = lane >> 2;          // deg group, handles deg 4dg..4dg+3
    const int bb   = lane & 3;
    const int col  = warp * 4 + bb;      // warp-private batch column

    const char* Ac = (const char*)As + col * 4;
    char*       Aw = (char*)As + col * 4 + IN_SIZE * ROWB;

    const uint4* pp = (const uint4*)g_pairs + dg * 2;

    uint4 c0[4], c1[4];
    #pragma unroll
    for (int u = 0; u < 4; u++) { c0[u] = pp[u * 16]; c1[u] = pp[u * 16 + 1]; }
    pp += 64;

    for (int g = 0; g < NGROUPS; g++) {
        uint4 n0[4], n1[4];
        #pragma unroll
        for (int u = 0; u < 4; u++) { n0[u] = pp[u * 16]; n1[u] = pp[u * 16 + 1]; }
        pp += 64;

        if (s_flags[g] == 0u) {
            // ---- FAST: 4 independent nodes; all loads precede all stores ----
            float s[4];
            #pragma unroll
            for (int u = 0; u < 4; u++) {
                uint4 pa = c0[u], pb = c1[u];
                float v0 = *(const float*)(Ac + pa.x);
                float v1 = *(const float*)(Ac + pa.z);
                float v2 = *(const float*)(Ac + pb.x);
                float v3 = *(const float*)(Ac + pb.z);
                float a0 = __uint_as_float(pa.y) * v0 + __uint_as_float(pa.w) * v1;
                float a1 = __uint_as_float(pb.y) * v2 + __uint_as_float(pb.w) * v3;
                s[u] = a0 + a1;
            }
            #pragma unroll
            for (int u = 0; u < 4; u++) s[u] = ftanh(wredux(s[u]));
            #pragma unroll
            for (int u = 0; u < 4; u++) *(float*)(Aw + u * ROWB) = s[u];
        } else {
            // ---- SERIAL: in-group dependency; strict node order ----
            #pragma unroll
            for (int u = 0; u < 4; u++) {
                uint4 pa = c0[u], pb = c1[u];
                float v0 = *(const float*)(Ac + pa.x);
                float v1 = *(const float*)(Ac + pa.z);
                float v2 = *(const float*)(Ac + pb.x);
                float v3 = *(const float*)(Ac + pb.z);
                float a0 = __uint_as_float(pa.y) * v0 + __uint_as_float(pa.w) * v1;
                float a1 = __uint_as_float(pb.y) * v2 + __uint_as_float(pb.w) * v3;
                float t = ftanh(wredux(a0 + a1));
                *(float*)(Aw + u * ROWB) = t;
            }
        }
        Aw += 4 * ROWB;
        #pragma unroll
        for (int u = 0; u < 4; u++) { c0[u] = n0[u]; c1[u] = n1[u]; }
    }

    // ---- Emit last OUT_SIZE node outputs: out[o][b0+col] ----
    #pragma unroll
    for (int it = 0; it < 2; it++) {
        int o = it * 8 + dg;
        float v = *(const float*)((const char*)As +
                     (size_t)(IN_SIZE + N_NODES - OUT_SIZE + o) * ROWB + col * 4);
        out[(size_t)o * BATCH + b0 + col] = v;
    }
}

extern "C" void kernel_launch(void* const* d_in, const int* in_sizes, int n_in,
                              void* d_out, int out_size) {
    const float* x   = (const float*)d_in[0];   // [16384, 256] f32
    const float* w   = (const float*)d_in[1];   // [1024, 32]   f32
    const int*   idx = (const int*)  d_in[2];   // [1024, 32]   i32
    float*       out = (float*)d_out;           // [16, 16384]  f32

    cudaFuncSetAttribute(ne_kernel, cudaFuncAttributeMaxDynamicSharedMemorySize, SMEM_BYTES);

    int pack_elems = N_NODES * DEG + 256;
    pack_pairs<<<(pack_elems + 255) / 256, 256>>>(idx, w);
    mark_flags<<<NGROUPS, 96>>>(idx);
    ne_kernel<<<BATCH / BT, 256, SMEM_BYTES>>>(x, out);
}

// round 3
// speedup vs baseline: 1.3899x; 1.2320x over previous
#include <cuda_runtime.h>
#include <cstdint>

#define IN_SIZE  256
#define N_NODES  1024
#define DEG      32
#define BATCH    16384
#define OUT_SIZE 16

#define BT      40                      // batch columns per CTA
#define NWARP   10                      // BT/4 warps
#define STRIDE  41                      // words per activation row (odd -> spread banks)
#define ROWB    (STRIDE * 4)            // 164 bytes per row
#define NROWS   (IN_SIZE + N_NODES)     // 1280
#define NGROUPS (N_NODES / 4)           // 256
#define SMEM_ACT (NROWS * ROWB)         // 209,920 B
#define SMEM_BYTES (SMEM_ACT + NGROUPS * 4)
#define NCTA    ((BATCH + BT - 1) / BT) // 410

// (byte_offset = idx*ROWB, weight) pairs; +256 uint2 pad for prefetch overrun.
__device__ uint2    g_pairs[N_NODES * DEG + 256];
__device__ unsigned g_flags[NGROUPS];   // bit0: any in-group dep; bit1: pair-violating dep

__global__ void pack_pairs(const int* __restrict__ idx, const float* __restrict__ w) {
    int t = blockIdx.x * blockDim.x + threadIdx.x;
    if (t < N_NODES * DEG) {
        g_pairs[t] = make_uint2((unsigned)idx[t] * (unsigned)ROWB, __float_as_uint(w[t]));
    } else if (t < N_NODES * DEG + 256) {
        g_pairs[t] = make_uint2(0u, 0u);
    }
    if (t < NGROUPS) g_flags[t] = 0u;
}

// Group g = nodes 4g..4g+3.
//   bit0: any node 4g+j (j=1..3) reads row >= 256+4g          (in-group dep)
//   bit1: node 4g+1 reads row 256+4g  OR  node 4g+3 reads 256+4g+2  (breaks pair mode)
__global__ void mark_flags(const int* __restrict__ idx) {
    int g = blockIdx.x;            // NGROUPS blocks
    int j = 1 + (threadIdx.x >> 5);
    int d = threadIdx.x & 31;
    int r = idx[(4 * g + j) * DEG + d];
    unsigned m = 0;
    if (r >= IN_SIZE + 4 * g) m |= 1u;
    if ((j == 1 && r >= IN_SIZE + 4 * g) || (j == 3 && r >= IN_SIZE + 4 * g + 2)) m |= 2u;
    if (m) atomicOr(&g_flags[g], m);
}

// Exact tanh(x) = 1 - 2/(exp(2x)+1); 2x MUFU, ~1e-6 abs error, saturates correctly.
__device__ __forceinline__ float ftanh(float x) {
    float e = __expf(2.0f * x);
    return 1.0f - __fdividef(2.0f, e + 1.0f);
}

__device__ __forceinline__ float wredux(float s) {
    s += __shfl_xor_sync(0xffffffffu, s, 4);
    s += __shfl_xor_sync(0xffffffffu, s, 8);
    s += __shfl_xor_sync(0xffffffffu, s, 16);
    return s;   // bit-identical across the 8 dg lanes
}

extern __shared__ float As[];   // [NROWS][STRIDE] activations + flag cache

__global__ void __launch_bounds__(32 * NWARP, 1)
ne_kernel(const float* __restrict__ x, float* __restrict__ out) {
    const int tid = threadIdx.x;
    const int b0  = blockIdx.x * BT;
    unsigned* s_flags = (unsigned*)(As + NROWS * STRIDE);

    // ---- Stage network inputs transposed: As[i][bl] = x[b0+bl][i] ----
    {
        int bl = tid >> 3;          // 0..39
        int ts = tid & 7;
        if (b0 + bl < BATCH) {
            const float4* xr = (const float4*)(x + (size_t)(b0 + bl) * IN_SIZE);
            #pragma unroll
            for (int k = ts; k < IN_SIZE / 4; k += 8) {
                float4 v = xr[k];
                int i = k * 4;
                As[(i + 0) * STRIDE + bl] = v.x;
                As[(i + 1) * STRIDE + bl] = v.y;
                As[(i + 2) * STRIDE + bl] = v.z;
                As[(i + 3) * STRIDE + bl] = v.w;
            }
        } else {
            #pragma unroll
            for (int k = ts; k < IN_SIZE / 4; k += 8) {
                int i = k * 4;
                As[(i + 0) * STRIDE + bl] = 0.f;
                As[(i + 1) * STRIDE + bl] = 0.f;
                As[(i + 2) * STRIDE + bl] = 0.f;
                As[(i + 3) * STRIDE + bl] = 0.f;
            }
        }
        if (tid < NGROUPS) s_flags[tid] = g_flags[tid];
    }
    __syncthreads();

    // ---- Lane layout: 8 deg-groups x 4 batch cols per warp; 10 warps = 40 cols ----
    const int lane = tid & 31;
    const int warp = tid >> 5;
    const int dg   = lane >> 2;          // deg group: degrees 4dg..4dg+3
    const int bb   = lane & 3;
    const int col  = warp * 4 + bb;      // warp-private batch column (0..39)

    const char* Ac = (const char*)As + col * 4;
    char*       Aw = (char*)As + col * 4 + IN_SIZE * ROWB;

    const uint4* pp = (const uint4*)g_pairs + dg * 2;

    uint4 c0[4], c1[4];
    #pragma unroll
    for (int u = 0; u < 4; u++) { c0[u] = pp[u * 16]; c1[u] = pp[u * 16 + 1]; }
    pp += 64;

    for (int g = 0; g < NGROUPS; g++) {
        uint4 n0[4], n1[4];
        #pragma unroll
        for (int u = 0; u < 4; u++) { n0[u] = pp[u * 16]; n1[u] = pp[u * 16 + 1]; }
        pp += 64;

        unsigned f = s_flags[g];
        if (f == 0u) {
            // ---- FAST: 4 independent nodes; all loads precede all stores ----
            float s[4];
            #pragma unroll
            for (int u = 0; u < 4; u++) {
                uint4 pa = c0[u], pb = c1[u];
                float v0 = *(const float*)(Ac + pa.x);
                float v1 = *(const float*)(Ac + pa.z);
                float v2 = *(const float*)(Ac + pb.x);
                float v3 = *(const float*)(Ac + pb.z);
                float a0 = __uint_as_float(pa.y) * v0 + __uint_as_float(pa.w) * v1;
                float a1 = __uint_as_float(pb.y) * v2 + __uint_as_float(pb.w) * v3;
                s[u] = a0 + a1;
            }
            #pragma unroll
            for (int u = 0; u < 4; u++) s[u] = ftanh(wredux(s[u]));
            #pragma unroll
            for (int u = 0; u < 4; u++) *(float*)(Aw + u * ROWB) = s[u];
        } else if (!(f & 2u)) {
            // ---- PAIR: pairs (0,1) and (2,3) internally clean; cross-pair dep
            //      handled by program order (pair0 stores precede pair1 loads). ----
            #pragma unroll
            for (int h = 0; h < 2; h++) {
                float s[2];
                #pragma unroll
                for (int u = 0; u < 2; u++) {
                    uint4 pa = c0[2 * h + u], pb = c1[2 * h + u];
                    float v0 = *(const float*)(Ac + pa.x);
                    float v1 = *(const float*)(Ac + pa.z);
                    float v2 = *(const float*)(Ac + pb.x);
                    float v3 = *(const float*)(Ac + pb.z);
                    float a0 = __uint_as_float(pa.y) * v0 + __uint_as_float(pa.w) * v1;
                    float a1 = __uint_as_float(pb.y) * v2 + __uint_as_float(pb.w) * v3;
                    s[u] = a0 + a1;
                }
                #pragma unroll
                for (int u = 0; u < 2; u++) s[u] = ftanh(wredux(s[u]));
                *(float*)(Aw + (2 * h + 0) * ROWB) = s[0];
                *(float*)(Aw + (2 * h + 1) * ROWB) = s[1];
            }
        } else {
            // ---- SERIAL: strict node order ----
            #pragma unroll
            for (int u = 0; u < 4; u++) {
                uint4 pa = c0[u], pb = c1[u];
                float v0 = *(const float*)(Ac + pa.x);
                float v1 = *(const float*)(Ac + pa.z);
                float v2 = *(const float*)(Ac + pb.x);
                float v3 = *(const float*)(Ac + pb.z);
                float a0 = __uint_as_float(pa.y) * v0 + __uint_as_float(pa.w) * v1;
                float a1 = __uint_as_float(pb.y) * v2 + __uint_as_float(pb.w) * v3;
                float t = ftanh(wredux(a0 + a1));
                *(float*)(Aw + u * ROWB) = t;
            }
        }
        Aw += 4 * ROWB;
        #pragma unroll
        for (int u = 0; u < 4; u++) { c0[u] = n0[u]; c1[u] = n1[u]; }
    }

    // ---- Emit last OUT_SIZE node outputs: out[o][b0+col] ----
    if (b0 + col < BATCH) {
        #pragma unroll
        for (int it = 0; it < 2; it++) {
            int o = it * 8 + dg;
            float v = *(const float*)((const char*)As +
                         (size_t)(IN_SIZE + N_NODES - OUT_SIZE + o) * ROWB + col * 4);
            out[(size_t)o * BATCH + b0 + col] = v;
        }
    }
}

extern "C" void kernel_launch(void* const* d_in, const int* in_sizes, int n_in,
                              void* d_out, int out_size) {
    const float* x   = (const float*)d_in[0];   // [16384, 256] f32
    const float* w   = (const float*)d_in[1];   // [1024, 32]   f32
    const int*   idx = (const int*)  d_in[2];   // [1024, 32]   i32
    float*       out = (float*)d_out;           // [16, 16384]  f32

    cudaFuncSetAttribute(ne_kernel, cudaFuncAttributeMaxDynamicSharedMemorySize, SMEM_BYTES);

    int pack_elems = N_NODES * DEG + 256;
    pack_pairs<<<(pack_elems + 255) / 256, 256>>>(idx, w);
    mark_flags<<<NGROUPS, 96>>>(idx);
    ne_kernel<<<NCTA, 32 * NWARP, SMEM_BYTES>>>(x, out);
}